// round 2
// baseline (speedup 1.0000x reference)
#include <cuda_runtime.h>
#include <math.h>
#include <stdint.h>

// Problem dims
#define B_   1024
#define Z_   256
#define TD_  512
#define CF_  1024
#define A_   64
#define R_   128
#define T_   64
#define G_   4096   // 4*CF

// Output layout: acts [B,T,A] | ts [B,T] | ress [B,T,R]
#define TS_BASE   (B_*T_*A_)
#define RESS_BASE (TS_BASE + B_*T_)

// ---------------- scratch (device globals; no allocation allowed) ------------
__device__ float g_trec[B_*TD_];
__device__ float g_Pa[B_*G_];
__device__ float g_Pr[B_*G_];
__device__ float g_Pt[B_*G_];
__device__ float g_hA[2][B_*CF_];
__device__ float g_hR[2][B_*CF_];
__device__ float g_hT[2][B_*CF_];
__device__ float g_cA[B_*CF_];
__device__ float g_cR[B_*CF_];
__device__ float g_cT[B_*CF_];
__device__ float g_hidden[B_*(CF_/2)];
__device__ int   g_actidx[B_];
__device__ int   g_residx[B_];
__device__ float g_tsv[B_];

__device__ unsigned g_bar_count = 0;
__device__ unsigned g_bar_gen   = 0;

// ---------------- software grid barrier (co-resident grid guaranteed) --------
__device__ __forceinline__ void grid_sync() {
    __syncthreads();
    if (threadIdx.x == 0) {
        __threadfence();
        unsigned gen = *(volatile unsigned*)&g_bar_gen;
        if (atomicAdd(&g_bar_count, 1u) == gridDim.x - 1) {
            g_bar_count = 0;
            __threadfence();
            atomicAdd(&g_bar_gen, 1u);   // release
        } else {
            while (*(volatile unsigned*)&g_bar_gen == gen) __nanosleep(64);
        }
        __threadfence();
    }
    __syncthreads();
}

// ---------------- 128x128 tile GEMM core: acc += A[bm:,:K] @ B[bn:,:K]^T -----
__device__ __forceinline__ void gemm128(
    const float* __restrict__ A, int lda,
    const float* __restrict__ B, int ldb,
    int K, int bm, int bn,
    float* sA, float* sB, float acc[8][8])
{
    const int tid  = threadIdx.x;
    const int tx   = tid & 15, ty = tid >> 4;
    const int lrow = tid >> 1;
    const int lseg = (tid & 1) * 2;
    const bool bvec = ((ldb & 3) == 0);

    for (int kb = 0; kb < K; kb += 16) {
        #pragma unroll
        for (int r = 0; r < 2; r++) {
            int seg = lseg + r;
            float4 v = *(const float4*)&A[(size_t)(bm + lrow) * lda + kb + seg * 4];
            sA[(seg*4+0)*128 + lrow] = v.x; sA[(seg*4+1)*128 + lrow] = v.y;
            sA[(seg*4+2)*128 + lrow] = v.z; sA[(seg*4+3)*128 + lrow] = v.w;
        }
        #pragma unroll
        for (int r = 0; r < 2; r++) {
            int seg = lseg + r;
            const float* bp = &B[(size_t)(bn + lrow) * ldb + kb + seg * 4];
            float4 v;
            if (bvec) v = *(const float4*)bp;
            else { v.x = bp[0]; v.y = bp[1]; v.z = bp[2]; v.w = bp[3]; }
            sB[(seg*4+0)*128 + lrow] = v.x; sB[(seg*4+1)*128 + lrow] = v.y;
            sB[(seg*4+2)*128 + lrow] = v.z; sB[(seg*4+3)*128 + lrow] = v.w;
        }
        __syncthreads();
        #pragma unroll
        for (int k = 0; k < 16; k++) {
            float a[8], b[8];
            *(float4*)&a[0] = *(const float4*)&sA[k*128 + ty*8];
            *(float4*)&a[4] = *(const float4*)&sA[k*128 + ty*8 + 4];
            *(float4*)&b[0] = *(const float4*)&sB[k*128 + tx*8];
            *(float4*)&b[4] = *(const float4*)&sB[k*128 + tx*8 + 4];
            #pragma unroll
            for (int i = 0; i < 8; i++)
                #pragma unroll
                for (int j = 0; j < 8; j++)
                    acc[i][j] += a[i] * b[j];
        }
        __syncthreads();
    }
}

// Same core but B rows are gate-interleaved: n_local = j_local*4 + gate,
// Whh row = gate*CF + j0 + j_local. ldb fixed = CF_ (aligned).
__device__ __forceinline__ void gemm128_gates(
    const float* __restrict__ A,
    const float* __restrict__ Whh,
    int bm, int j0,
    float* sA, float* sB, float acc[8][8])
{
    const int tid  = threadIdx.x;
    const int tx   = tid & 15, ty = tid >> 4;
    const int lrow = tid >> 1;
    const int lseg = (tid & 1) * 2;
    const int brow = (lrow & 3) * CF_ + j0 + (lrow >> 2);

    for (int kb = 0; kb < CF_; kb += 16) {
        #pragma unroll
        for (int r = 0; r < 2; r++) {
            int seg = lseg + r;
            float4 v = *(const float4*)&A[(size_t)(bm + lrow) * CF_ + kb + seg * 4];
            sA[(seg*4+0)*128 + lrow] = v.x; sA[(seg*4+1)*128 + lrow] = v.y;
            sA[(seg*4+2)*128 + lrow] = v.z; sA[(seg*4+3)*128 + lrow] = v.w;
        }
        #pragma unroll
        for (int r = 0; r < 2; r++) {
            int seg = lseg + r;
            float4 v = *(const float4*)&Whh[(size_t)brow * CF_ + kb + seg * 4];
            sB[(seg*4+0)*128 + lrow] = v.x; sB[(seg*4+1)*128 + lrow] = v.y;
            sB[(seg*4+2)*128 + lrow] = v.z; sB[(seg*4+3)*128 + lrow] = v.w;
        }
        __syncthreads();
        #pragma unroll
        for (int k = 0; k < 16; k++) {
            float a[8], b[8];
            *(float4*)&a[0] = *(const float4*)&sA[k*128 + ty*8];
            *(float4*)&a[4] = *(const float4*)&sA[k*128 + ty*8 + 4];
            *(float4*)&b[0] = *(const float4*)&sB[k*128 + tx*8];
            *(float4*)&b[4] = *(const float4*)&sB[k*128 + tx*8 + 4];
            #pragma unroll
            for (int i = 0; i < 8; i++)
                #pragma unroll
                for (int j = 0; j < 8; j++)
                    acc[i][j] += a[i] * b[j];
        }
        __syncthreads();
    }
}

// ---------------- 64x64 tile GEMM core (full K) ------------------------------
__device__ __forceinline__ void gemm64(
    const float* __restrict__ A, int lda,
    const float* __restrict__ B, int ldb,
    int K, int bm, int bn,
    float* sA, float* sB, float acc[4][4])
{
    const int tid  = threadIdx.x;
    const int tx   = tid & 15, ty = tid >> 4;
    const int lrow = tid >> 2;
    const int lseg = tid & 3;

    for (int kb = 0; kb < K; kb += 16) {
        float4 av = *(const float4*)&A[(size_t)(bm + lrow) * lda + kb + lseg * 4];
        sA[(lseg*4+0)*64 + lrow] = av.x; sA[(lseg*4+1)*64 + lrow] = av.y;
        sA[(lseg*4+2)*64 + lrow] = av.z; sA[(lseg*4+3)*64 + lrow] = av.w;
        float4 bv = *(const float4*)&B[(size_t)(bn + lrow) * ldb + kb + lseg * 4];
        sB[(lseg*4+0)*64 + lrow] = bv.x; sB[(lseg*4+1)*64 + lrow] = bv.y;
        sB[(lseg*4+2)*64 + lrow] = bv.z; sB[(lseg*4+3)*64 + lrow] = bv.w;
        __syncthreads();
        #pragma unroll
        for (int k = 0; k < 16; k++) {
            float a[4], b[4];
            *(float4*)&a[0] = *(const float4*)&sA[k*64 + ty*4];
            *(float4*)&b[0] = *(const float4*)&sB[k*64 + tx*4];
            #pragma unroll
            for (int i = 0; i < 4; i++)
                #pragma unroll
                for (int j = 0; j < 4; j++)
                    acc[i][j] += a[i] * b[j];
        }
        __syncthreads();
    }
}

// ---------------- fused LSTM stage: h_new,c = cell(h_old@Whh^T + P + onehots)
__device__ void lstm_stage(
    const float* __restrict__ hin, const float* __restrict__ Whh,
    const float* __restrict__ P,   const float* __restrict__ Wih, int ldw,
    const int* __restrict__ idx1, int c1b,
    const int* __restrict__ idx2, int c2b,
    const float* __restrict__ tsvp, int tscol,
    float* __restrict__ hout, float* __restrict__ c,
    float* sA, float* sB)
{
    const int tid = threadIdx.x;
    const int tx  = tid & 15, ty = tid >> 4;

    for (int tile = blockIdx.x; tile < 256; tile += gridDim.x) {
        int bm = (tile >> 5) * 128;
        int j0 = (tile & 31) * 32;

        float acc[8][8];
        #pragma unroll
        for (int i = 0; i < 8; i++)
            #pragma unroll
            for (int j = 0; j < 8; j++) acc[i][j] = 0.f;

        gemm128_gates(hin, Whh, bm, j0, sA, sB, acc);

        #pragma unroll
        for (int i = 0; i < 8; i++) {
            int gm = bm + ty*8 + i;
            int col1 = c1b + idx1[gm];
            int col2 = (idx2 != nullptr) ? (c2b + idx2[gm]) : 0;
            float tv = (tscol >= 0) ? tsvp[gm] : 0.f;
            #pragma unroll
            for (int jp = 0; jp < 2; jp++) {
                int j = j0 + tx*2 + jp;
                float g4[4];
                #pragma unroll
                for (int g = 0; g < 4; g++) {
                    int n = g * CF_ + j;
                    float v = acc[i][jp*4 + g]
                            + P[(size_t)gm * G_ + n]
                            + Wih[(size_t)n * ldw + col1];
                    if (idx2 != nullptr) v += Wih[(size_t)n * ldw + col2];
                    if (tscol >= 0)      v += tv * Wih[(size_t)n * ldw + tscol];
                    g4[g] = v;
                }
                float ig = 1.f / (1.f + expf(-g4[0]));
                float fg = 1.f / (1.f + expf(-g4[1]));
                float gg = tanhf(g4[2]);
                float og = 1.f / (1.f + expf(-g4[3]));
                size_t off = (size_t)gm * CF_ + j;
                float cn = fg * c[off] + ig * gg;
                c[off] = cn;
                hout[off] = og * tanhf(cn);
            }
        }
    }
}

// ---------------- the whole decoder as ONE persistent kernel -----------------
__global__ __launch_bounds__(256, 2) void decoder_all(
    const float* __restrict__ z,
    const float* __restrict__ z2t_w, const float* __restrict__ z2t_b,
    const float* __restrict__ Wih_a, const float* __restrict__ Whh_a, const float* __restrict__ b_a,
    const float* __restrict__ Wih_r, const float* __restrict__ Whh_r, const float* __restrict__ b_r,
    const float* __restrict__ Wih_t, const float* __restrict__ Whh_t, const float* __restrict__ b_t,
    const float* __restrict__ e2act_w, const float* __restrict__ e2act_b,
    const float* __restrict__ e2res_w, const float* __restrict__ e2res_b,
    const float* __restrict__ e2ts_w1, const float* __restrict__ e2ts_b1,
    const float* __restrict__ e2ts_w2, const float* __restrict__ e2ts_b2,
    float* __restrict__ out)
{
    __shared__ float sA[16*128];
    __shared__ float sB[16*128];
    const int tid = threadIdx.x;
    const int bid = blockIdx.x;
    const int nb  = gridDim.x;
    const int nthr = nb * 256;
    const int gthr = bid * 256 + tid;
    const int lane = tid & 31;
    const int wid  = tid >> 5;

    // ---- phase 0: init state + trec = relu(z @ z2t_w^T + b) ----
    for (int i = gthr; i < B_*CF_; i += nthr) {
        g_hA[0][i] = 0.f; g_hA[1][i] = 0.f; g_cA[i] = 0.f;
        g_hR[0][i] = 0.f; g_hR[1][i] = 0.f; g_cR[i] = 0.f;
        g_hT[0][i] = 0.f; g_hT[1][i] = 0.f; g_cT[i] = 0.f;
    }
    for (int i = gthr; i < B_; i += nthr) {
        g_actidx[i] = A_ - 1; g_residx[i] = R_ - 1; g_tsv[i] = 0.f;
    }
    for (int tile = bid; tile < 32; tile += nb) {          // 8 x 4 tiles
        int bm = (tile >> 2) * 128, bn = (tile & 3) * 128;
        float acc[8][8];
        #pragma unroll
        for (int i = 0; i < 8; i++)
            #pragma unroll
            for (int j = 0; j < 8; j++) acc[i][j] = 0.f;
        gemm128(z, Z_, z2t_w, Z_, Z_, bm, bn, sA, sB, acc);
        const int tx = tid & 15, ty = tid >> 4;
        #pragma unroll
        for (int i = 0; i < 8; i++) {
            int gm = bm + ty*8 + i;
            #pragma unroll
            for (int j = 0; j < 8; j++) {
                int gn = bn + tx*8 + j;
                g_trec[(size_t)gm * TD_ + gn] = fmaxf(acc[i][j] + z2t_b[gn], 0.f);
            }
        }
    }
    grid_sync();

    // ---- phase 1: P_* = trec @ Wih_*[:, :512]^T + b_* (768 tiles) ----
    for (int tile = bid; tile < 768; tile += nb) {
        int which = tile >> 8;          // /256
        int rem   = tile & 255;
        int bm = (rem >> 5) * 128, bn = (rem & 31) * 128;
        const float* Wih  = (which == 0) ? Wih_a : (which == 1) ? Wih_r : Wih_t;
        const float* bias = (which == 0) ? b_a   : (which == 1) ? b_r   : b_t;
        float* P          = (which == 0) ? g_Pa  : (which == 1) ? g_Pr  : g_Pt;
        int ldb = (which == 0) ? (TD_+A_) : (which == 1) ? (TD_+A_+R_) : (TD_+A_+1);
        float acc[8][8];
        #pragma unroll
        for (int i = 0; i < 8; i++)
            #pragma unroll
            for (int j = 0; j < 8; j++) acc[i][j] = 0.f;
        gemm128(g_trec, TD_, Wih, ldb, TD_, bm, bn, sA, sB, acc);
        const int tx = tid & 15, ty = tid >> 4;
        #pragma unroll
        for (int i = 0; i < 8; i++) {
            int gm = bm + ty*8 + i;
            #pragma unroll
            for (int j = 0; j < 8; j++) {
                int gn = bn + tx*8 + j;
                P[(size_t)gm * G_ + gn] = acc[i][j] + bias[gn];
            }
        }
    }
    grid_sync();

    // ---- time loop ----
    for (int t = 0; t < T_; t++) {
        int p = t & 1, q = 1 - p;

        // ===== stage a =====
        lstm_stage(g_hA[p], Whh_a, g_Pa, Wih_a, TD_ + A_,
                   g_actidx, TD_, nullptr, 0, nullptr, -1,
                   g_hA[q], g_cA, sA, sB);
        grid_sync();

        // act head: 64 blocks x 16 rows x 64 cols, K=1024; + argmax
        for (int blk = bid; blk < 64; blk += nb) {
            int m0 = blk * 16;
            float acc4[4] = {0.f, 0.f, 0.f, 0.f};
            const float* h = g_hA[q];
            for (int kb = 0; kb < CF_; kb += 32) {
                if (tid < 128) {
                    int r = tid >> 3, c4 = (tid & 7) * 4;
                    float4 v = *(const float4*)&h[(size_t)(m0 + r) * CF_ + kb + c4];
                    sA[r*32 + c4+0] = v.x; sA[r*32 + c4+1] = v.y;
                    sA[r*32 + c4+2] = v.z; sA[r*32 + c4+3] = v.w;
                }
                #pragma unroll
                for (int qq = 0; qq < 2; qq++) {
                    int idx = tid * 2 + qq;          // 512 float4s
                    int cc = idx >> 3, k4 = (idx & 7) * 4;
                    float4 v = *(const float4*)&e2act_w[(size_t)cc * CF_ + kb + k4];
                    sB[(k4+0)*64 + cc] = v.x; sB[(k4+1)*64 + cc] = v.y;
                    sB[(k4+2)*64 + cc] = v.z; sB[(k4+3)*64 + cc] = v.w;
                }
                __syncthreads();
                int r = tid >> 4, c0 = (tid & 15) * 4;
                #pragma unroll
                for (int k = 0; k < 32; k++) {
                    float a = sA[r*32 + k];
                    acc4[0] += a * sB[k*64 + c0+0];
                    acc4[1] += a * sB[k*64 + c0+1];
                    acc4[2] += a * sB[k*64 + c0+2];
                    acc4[3] += a * sB[k*64 + c0+3];
                }
                __syncthreads();
            }
            int r = tid >> 4, c0 = (tid & 15) * 4;
            #pragma unroll
            for (int j = 0; j < 4; j++) {
                float v = acc4[j] + e2act_b[c0 + j];
                sA[r*64 + c0 + j] = v;
                out[(size_t)(m0 + r) * (T_*A_) + t*A_ + c0 + j] = v;
            }
            __syncthreads();
            if (tid < 16) {
                float bv = -INFINITY; int bi = 0;
                for (int n = 0; n < A_; n++) {
                    float v = sA[tid*64 + n];
                    if (v > bv) { bv = v; bi = n; }
                }
                g_actidx[m0 + tid] = bi;
            }
            __syncthreads();
        }
        grid_sync();

        // ===== stage r =====
        lstm_stage(g_hR[p], Whh_r, g_Pr, Wih_r, TD_ + A_ + R_,
                   g_actidx, TD_, g_residx, TD_ + A_, nullptr, -1,
                   g_hR[q], g_cR, sA, sB);
        grid_sync();

        // res head: 128 blocks x 8 rows x 128 cols, K=1024; + argmax
        for (int blk = bid; blk < 128; blk += nb) {
            int m0 = blk * 8;
            float acc4[4] = {0.f, 0.f, 0.f, 0.f};
            const float* h = g_hR[q];
            for (int kb = 0; kb < CF_; kb += 16) {
                if (tid < 32) {
                    int r = tid >> 2, c4 = (tid & 3) * 4;
                    float4 v = *(const float4*)&h[(size_t)(m0 + r) * CF_ + kb + c4];
                    sA[r*16 + c4+0] = v.x; sA[r*16 + c4+1] = v.y;
                    sA[r*16 + c4+2] = v.z; sA[r*16 + c4+3] = v.w;
                }
                #pragma unroll
                for (int qq = 0; qq < 2; qq++) {
                    int idx = tid * 2 + qq;          // 512 float4s
                    int cc = idx >> 2, k4 = (idx & 3) * 4;
                    float4 v = *(const float4*)&e2res_w[(size_t)cc * CF_ + kb + k4];
                    sB[(k4+0)*128 + cc] = v.x; sB[(k4+1)*128 + cc] = v.y;
                    sB[(k4+2)*128 + cc] = v.z; sB[(k4+3)*128 + cc] = v.w;
                }
                __syncthreads();
                int r = tid >> 5, c0 = (tid & 31) * 4;
                #pragma unroll
                for (int k = 0; k < 16; k++) {
                    float a = sA[r*16 + k];
                    acc4[0] += a * sB[k*128 + c0+0];
                    acc4[1] += a * sB[k*128 + c0+1];
                    acc4[2] += a * sB[k*128 + c0+2];
                    acc4[3] += a * sB[k*128 + c0+3];
                }
                __syncthreads();
            }
            int r = tid >> 5, c0 = (tid & 31) * 4;
            #pragma unroll
            for (int j = 0; j < 4; j++) {
                float v = acc4[j] + e2res_b[c0 + j];
                sA[r*128 + c0 + j] = v;
                out[RESS_BASE + (size_t)(m0 + r) * (T_*R_) + t*R_ + c0 + j] = v;
            }
            __syncthreads();
            if (tid < 8) {
                float bv = -INFINITY; int bi = 0;
                for (int n = 0; n < R_; n++) {
                    float v = sA[tid*128 + n];
                    if (v > bv) { bv = v; bi = n; }
                }
                g_residx[m0 + tid] = bi;
            }
            __syncthreads();
        }
        grid_sync();

        // ===== stage t =====
        lstm_stage(g_hT[p], Whh_t, g_Pt, Wih_t, TD_ + A_ + 1,
                   g_actidx, TD_, nullptr, 0, g_tsv, TD_ + A_,
                   g_hT[q], g_cT, sA, sB);
        grid_sync();

        // ts hidden = relu(hT @ w1^T + b1): 16 x 8 tiles of 64x64, K=1024
        for (int tile = bid; tile < 128; tile += nb) {
            int bm = (tile >> 3) * 64, bn = (tile & 7) * 64;
            float acc[4][4];
            #pragma unroll
            for (int i = 0; i < 4; i++)
                #pragma unroll
                for (int j = 0; j < 4; j++) acc[i][j] = 0.f;
            gemm64(g_hT[q], CF_, e2ts_w1, CF_, CF_, bm, bn, sA, sB, acc);
            const int tx = tid & 15, ty = tid >> 4;
            #pragma unroll
            for (int i = 0; i < 4; i++) {
                int gm = bm + ty*4 + i;
                #pragma unroll
                for (int j = 0; j < 4; j++) {
                    int gn = bn + tx*4 + j;
                    g_hidden[(size_t)gm * (CF_/2) + gn] =
                        fmaxf(acc[i][j] + e2ts_b1[gn], 0.f);
                }
            }
        }
        grid_sync();

        // ts = hidden . w2 + b2 (warp per row)
        for (int m = bid * 8 + wid; m < B_; m += nb * 8) {
            const float* hrow = &g_hidden[(size_t)m * (CF_/2)];
            float s = 0.f;
            for (int j = lane; j < CF_/2; j += 32) s += hrow[j] * e2ts_w2[j];
            #pragma unroll
            for (int off = 16; off; off >>= 1)
                s += __shfl_down_sync(0xffffffffu, s, off);
            if (lane == 0) {
                float v = s + e2ts_b2[0];
                g_tsv[m] = v;
                out[TS_BASE + (size_t)m * T_ + t] = v;
            }
        }
        grid_sync();
    }

    // ---- final softmaxes (warp per row) ----
    for (int r = bid * 8 + wid; r < B_*T_; r += nb * 8) {      // acts, W=64
        float* row = out + (size_t)r * A_;
        float v0 = row[lane], v1 = row[lane + 32];
        float mx = fmaxf(v0, v1);
        #pragma unroll
        for (int off = 16; off; off >>= 1)
            mx = fmaxf(mx, __shfl_xor_sync(0xffffffffu, mx, off));
        float e0 = expf(v0 - mx), e1 = expf(v1 - mx);
        float s = e0 + e1;
        #pragma unroll
        for (int off = 16; off; off >>= 1)
            s += __shfl_xor_sync(0xffffffffu, s, off);
        float inv = 1.f / s;
        row[lane] = e0 * inv; row[lane + 32] = e1 * inv;
    }
    for (int r = bid * 8 + wid; r < B_*T_; r += nb * 8) {      // ress, W=128
        float* row = out + RESS_BASE + (size_t)r * R_;
        float v[4];
        float mx = -INFINITY;
        #pragma unroll
        for (int u = 0; u < 4; u++) { v[u] = row[lane + u*32]; mx = fmaxf(mx, v[u]); }
        #pragma unroll
        for (int off = 16; off; off >>= 1)
            mx = fmaxf(mx, __shfl_xor_sync(0xffffffffu, mx, off));
        float e[4]; float s = 0.f;
        #pragma unroll
        for (int u = 0; u < 4; u++) { e[u] = expf(v[u] - mx); s += e[u]; }
        #pragma unroll
        for (int off = 16; off; off >>= 1)
            s += __shfl_xor_sync(0xffffffffu, s, off);
        float inv = 1.f / s;
        #pragma unroll
        for (int u = 0; u < 4; u++) row[lane + u*32] = e[u] * inv;
    }
}

// ---------------- host -------------------------------------------------------
extern "C" void kernel_launch(void* const* d_in, const int* in_sizes, int n_in,
                              void* d_out, int out_size)
{
    const float* z        = (const float*)d_in[0];
    const float* z2t_w    = (const float*)d_in[1];
    const float* z2t_b    = (const float*)d_in[2];
    const float* Wih_a    = (const float*)d_in[3];
    const float* Whh_a    = (const float*)d_in[4];
    const float* b_a      = (const float*)d_in[5];
    const float* Wih_r    = (const float*)d_in[6];
    const float* Whh_r    = (const float*)d_in[7];
    const float* b_r      = (const float*)d_in[8];
    const float* Wih_t    = (const float*)d_in[9];
    const float* Whh_t    = (const float*)d_in[10];
    const float* b_t      = (const float*)d_in[11];
    const float* e2act_w  = (const float*)d_in[12];
    const float* e2act_b  = (const float*)d_in[13];
    const float* e2res_w  = (const float*)d_in[14];
    const float* e2res_b  = (const float*)d_in[15];
    const float* e2ts_w1  = (const float*)d_in[16];
    const float* e2ts_b1  = (const float*)d_in[17];
    const float* e2ts_w2  = (const float*)d_in[18];
    const float* e2ts_b2  = (const float*)d_in[19];
    float* out = (float*)d_out;

    int dev = 0;
    cudaGetDevice(&dev);
    int nsm = 0;
    cudaDeviceGetAttribute(&nsm, cudaDevAttrMultiProcessorCount, dev);
    int occ = 0;
    cudaOccupancyMaxActiveBlocksPerMultiprocessor(&occ, decoder_all, 256, 0);
    if (occ < 1) occ = 1;
    if (nsm < 1) nsm = 1;
    int nb = nsm * occ;          // guaranteed co-resident -> grid barrier safe

    decoder_all<<<nb, 256>>>(
        z, z2t_w, z2t_b,
        Wih_a, Whh_a, b_a,
        Wih_r, Whh_r, b_r,
        Wih_t, Whh_t, b_t,
        e2act_w, e2act_b, e2res_w, e2res_b,
        e2ts_w1, e2ts_b1, e2ts_w2, e2ts_b2,
        out);
}